// round 13
// baseline (speedup 1.0000x reference)
#include <cuda_runtime.h>
#include <cuda_bf16.h>
#include <cstdint>

// Problem shape (fixed by reference)
#define Bq   4
#define Sq   1024
#define Hq   32
#define Dq   128
#define SMAX 2048

// Flattened float32 output layout (confirmed R8): [new_ck | new_cks | new_cv | new_cvs]
static constexpr long long CK_ELEMS = (long long)SMAX * Hq * Bq * Dq;  // 33,554,432
static constexpr long long SC_ELEMS = (long long)SMAX * Hq * Bq;       //    262,144
static constexpr long long OFF_CK  = 0;
static constexpr long long OFF_CKS = OFF_CK  + CK_ELEMS;               // 33,554,432
static constexpr long long OFF_CV  = OFF_CKS + SC_ELEMS;               // 33,816,576
static constexpr long long OFF_CVS = OFF_CV  + CK_ELEMS;               // 67,371,008

// Grid partition. 2 rows/warp (quant) and 32 B/thread (tail) -> MLP 2 per thread.
// Quant & tail interleaved 4:1 per wave to keep the DRAM R/W mix balanced.
static constexpr int QUANT_BLOCKS = 16384;  // 2*131072 rows / (2 rows*8 warps)
static constexpr int TAIL_BLOCKS  = 4096;   // 2*16MB / (32 B/thread * 256)
static constexpr int MIX_BLOCKS   = QUANT_BLOCKS + TAIL_BLOCKS;  // 20480 = 4096*5
static constexpr int SCALE_BLOCKS = 256;
static constexpr int TOTAL_BLOCKS = MIX_BLOCKS + SCALE_BLOCKS;

__device__ __forceinline__ float4 quant_one(const float4 v, float& m_out)
{
    // abs-max via REDUX: IEEE order == unsigned order for abs values
    const float lm = fmaxf(fmaxf(fabsf(v.x), fabsf(v.y)),
                           fmaxf(fabsf(v.z), fabsf(v.w)));
    const float m = __uint_as_float(
        __reduce_max_sync(0xffffffffu, __float_as_uint(lm)));
    m_out = m;
    // IEEE-rn div/mul: the 127-vs-128 rounding decision must match XLA.
    const float t = __fdiv_rn(127.5f, m);
    float4 o;  // rint + saturate in float domain (exact on integers)
    o.x = fminf(fmaxf(rintf(__fmul_rn(v.x, t)), -128.0f), 127.0f);
    o.y = fminf(fmaxf(rintf(__fmul_rn(v.y, t)), -128.0f), 127.0f);
    o.z = fminf(fmaxf(rintf(__fmul_rn(v.z, t)), -128.0f), 127.0f);
    o.w = fminf(fmaxf(rintf(__fmul_rn(v.w, t)), -128.0f), 127.0f);
    return o;
}

__global__ void __launch_bounds__(256) kv_fused(
    const float*         __restrict__ key,
    const float*         __restrict__ val,
    const signed char*   __restrict__ ck,
    const signed char*   __restrict__ cv,
    const __nv_bfloat16* __restrict__ cks,
    const __nv_bfloat16* __restrict__ cvs,
    float*               __restrict__ out)
{
    const int bid = blockIdx.x;

    if (bid < MIX_BLOCKS) {
        const int g   = bid / 5;     // 4096 groups of (4 quant + 1 tail)
        const int rem = bid - g * 5;

        if (rem < 4) {
            // --------------------------------------------------------------
            // Quantize + transpose-scatter. 2 rows per warp, loads batched
            // front (MLP=2; two independent REDUX chains overlap).
            // --------------------------------------------------------------
            const int qbid = g * 4 + rem;                // [0, 16384)
            const int lane = threadIdx.x & 31;
            const int w    = qbid * 8 + (threadIdx.x >> 5);  // [0, 131072)
            const int R0   = 2 * w;                      // rows R0, R0+1
            const int ROWS = Bq * Sq * Hq;               // 131072 per tensor
            const bool isV = R0 >= ROWS;                 // pair never straddles
            const int  r0  = isV ? (R0 - ROWS) : R0;
            const int  r1  = r0 + 1;

            const float* srcT = isV ? val : key;
            // both loads issued before any dependent math
            const float4 v0 = __ldcs(reinterpret_cast<const float4*>(
                srcT + (long long)r0 * Dq) + lane);
            const float4 v1 = __ldcs(reinterpret_cast<const float4*>(
                srcT + (long long)r1 * Dq) + lane);

            float m0, m1;
            const float4 o0 = quant_one(v0, m0);
            const float4 o1 = quant_one(v1, m1);

            const long long dataOff  = isV ? OFF_CV  : OFF_CK;
            const long long scaleOff = isV ? OFF_CVS : OFF_CKS;

            const int b0 = r0 >> 15, sh0 = r0 & 32767;
            const int b1 = r1 >> 15, sh1 = r1 & 32767;

            __stcs(reinterpret_cast<float4*>(
                out + dataOff + (((long long)sh0 * Bq + b0) << 7)) + lane, o0);
            __stcs(reinterpret_cast<float4*>(
                out + dataOff + (((long long)sh1 * Bq + b1) << 7)) + lane, o1);

            if (lane == 0) {  // reference's bf16 round-trip of the scales
                out[scaleOff + (long long)sh0 * Bq + b0] =
                    __bfloat162float(__float2bfloat16(m0));
                out[scaleOff + (long long)sh1 * Bq + b1] =
                    __bfloat162float(__float2bfloat16(m1));
            }
        } else {
            // --------------------------------------------------------------
            // Untouched cache tail (s in [1024,2048)): int8 -> f32.
            // 32 int8 per thread via two independent uint4 loads (MLP=2).
            // --------------------------------------------------------------
            const long long HALF = (long long)Sq * Hq * Bq * Dq;  // 16,777,216
            const long long NTH  = HALF >> 5;                     // 524,288 /tensor
            const long long tid  = (long long)g * 256 + threadIdx.x;
            const bool isV = tid >= NTH;
            const long long i = ((isV ? tid - NTH : tid) << 5) + HALF;

            const signed char* srcT = isV ? cv : ck;
            const uint4 raw0 = __ldcs(reinterpret_cast<const uint4*>(srcT + i));
            const uint4 raw1 = __ldcs(reinterpret_cast<const uint4*>(srcT + i + 16));

            float4* dst = reinterpret_cast<float4*>(
                out + (isV ? OFF_CV : OFF_CK) + i);

            const unsigned w8[8] = {raw0.x, raw0.y, raw0.z, raw0.w,
                                    raw1.x, raw1.y, raw1.z, raw1.w};
            #pragma unroll
            for (int k = 0; k < 8; k++) {
                float4 f;
                f.x = (float)(signed char)( w8[k]        & 0xFF);
                f.y = (float)(signed char)((w8[k] >> 8)  & 0xFF);
                f.z = (float)(signed char)((w8[k] >> 16) & 0xFF);
                f.w = (float)(signed char)((w8[k] >> 24) & 0xFF);
                __stcs(dst + k, f);
            }
        }
    }
    else {
        // ------------------------------------------------------------------
        // Untouched scale tail: bf16 -> f32, 4 elems/thread.
        // ------------------------------------------------------------------
        const long long NEWS = (long long)Sq * Hq * Bq;  // 131,072
        const long long NV   = NEWS >> 2;
        const long long tid  = (long long)(bid - MIX_BLOCKS) * 256 + threadIdx.x;
        const bool isV = tid >= NV;
        const long long i = ((isV ? tid - NV : tid) << 2) + NEWS;

        const uint2 raw =
            __ldcs(reinterpret_cast<const uint2*>((isV ? cvs : cks) + i));
        float4 o;
        o.x = __bfloat162float(__ushort_as_bfloat16((unsigned short)(raw.x & 0xFFFF)));
        o.y = __bfloat162float(__ushort_as_bfloat16((unsigned short)(raw.x >> 16)));
        o.z = __bfloat162float(__ushort_as_bfloat16((unsigned short)(raw.y & 0xFFFF)));
        o.w = __bfloat162float(__ushort_as_bfloat16((unsigned short)(raw.y >> 16)));
        __stcs(reinterpret_cast<float4*>(out + (isV ? OFF_CVS : OFF_CKS) + i), o);
    }
}

// ===========================================================================
// Launch. Inputs: key f32, value f32, cached_key i8, cached_value i8,
//                 cached_key_scale bf16, cached_value_scale bf16
// ===========================================================================
extern "C" void kernel_launch(void* const* d_in, const int* in_sizes, int n_in,
                              void* d_out, int out_size)
{
    const float*         key = (const float*)d_in[0];
    const float*         val = (const float*)d_in[1];
    const signed char*   ck  = (const signed char*)d_in[2];
    const signed char*   cv  = (const signed char*)d_in[3];
    const __nv_bfloat16* cks = (const __nv_bfloat16*)d_in[4];
    const __nv_bfloat16* cvs = (const __nv_bfloat16*)d_in[5];
    float* out = (float*)d_out;

    kv_fused<<<TOTAL_BLOCKS, 256>>>(key, val, ck, cv, cks, cvs, out);
}